// round 9
// baseline (speedup 1.0000x reference)
#include <cuda_runtime.h>
#include <math.h>

#define BB 8
#define TT 2048
#define M_ROWS (BB*TT)   /* 16384 */
#define DVC 1024
#define DAC 128
#define IN_C 1152
#define D1C 512
#define D2C 128
#define DHP 264          /* 257 padded to mult of 8 */
#define DGC 128

typedef unsigned long long u64;

/* ---------------- scratch (static device globals; no allocs) ---------------- */
__device__ float g_y1[M_ROWS * D1C];
__device__ float g_xv2p[2 * M_ROWS * D2C];  // GEMM2 split-K raw partials
__device__ float g_proj[M_ROWS * DHP];
__device__ float g_qproj[M_ROWS * DHP];
__device__ float g_gwT[256 * DHP];
__device__ float g_g12[M_ROWS * 256];
__device__ float g_g1T[BB * DGC * TT];
__device__ float g_E[(size_t)BB * TT * TT]; // 134 MB
__device__ float g_denom[M_ROWS];
__device__ float g_x1p[2 * M_ROWS * DGC];   // adj split-K raw partials
__device__ float g_x2[M_ROWS * DGC];
__device__ float g_frame[M_ROWS];

/* ---------------- packed f32x2 helpers (Blackwell FFMA2) ---------------- */
__device__ __forceinline__ void ffma2(u64 &d, u64 a, u64 b) {
    asm("fma.rn.f32x2 %0, %1, %2, %0;" : "+l"(d) : "l"(a), "l"(b));
}
__device__ __forceinline__ u64 pack2(float x) {
    u64 r; asm("mov.b64 %0, {%1, %1};" : "=l"(r) : "f"(x)); return r;
}
__device__ __forceinline__ float2 unpk(u64 v) {
    float2 r; asm("mov.b64 {%0, %1}, %2;" : "=f"(r.x), "=f"(r.y) : "l"(v)); return r;
}

/* ---------------- generic 128x128x8 SGEMM, C = A[M,K] * B[N,K]^T ------------ */
struct GemmP {
    const float* A; const float* Bm; float* C;
    int K, lda, ldb, ldc;
    long aS, bS, cS;            // per-blockIdx.z strides
    long splitStride;           // split-K: offset between partial buffers
    const float* bias;
    const int* seq;
    float* denom;               // MODE2: atomic row-sum output
};

// MODE 0: C = leaky(acc + bias[n])
// MODE 1: C = acc
// MODE 2: similarity -> E (tile-skipped by seq_len) + fused row-sum atomics
// MODE 3: raw adj matmul partials, split-K over gridDim.x, K clamped to ceil8(L)
// MODE 4: raw partials, static split-K over gridDim.x (GEMM2)
template <int MODE>
__global__ __launch_bounds__(256, 2) void sgemm(GemmP p) {
    const int z = blockIdx.z;
    const int rowBase = blockIdx.y << 7;
    int colBase, split;
    if (MODE == 3 || MODE == 4) { colBase = 0; split = blockIdx.x; }
    else                        { colBase = blockIdx.x << 7; split = 0; }

    int L = 0;
    if (MODE == 2 || MODE == 3) L = p.seq[z];
    if (MODE == 2 && (rowBase >= L || colBase >= L)) return;   // tile never read
    if (MODE == 3 && rowBase >= L) return;                     // output rows masked

    int k_begin = 0, k_end = p.K >> 3;
    if (MODE == 3) {
        const int nk_eff = (L + 7) >> 3;      // E cols >= ceil8(L) are zero
        const int half   = (nk_eff + 1) >> 1;
        k_begin = split ? half : 0;
        k_end   = split ? nk_eff : half;
    } else if (MODE == 4) {
        const int half = (k_end + 1) >> 1;
        k_begin = split ? half : 0;
        k_end   = split ? k_end : half;
    }

    __shared__ u64   As2[2][8][128];   // A staged as duplicated f32 pairs (8KB/stage)
    __shared__ float Bs[2][8][128];
    const float* A  = p.A  + (long)z * p.aS;
    const float* Bm = p.Bm + (long)z * p.bS;
    float*       C  = p.C  + (long)z * p.cS + (long)split * p.splitStride;
    const int tid = threadIdx.x;
    const int tx = tid & 15, ty = tid >> 4;
    const int lr = tid >> 1;
    const int lc = (tid & 1) << 2;
    const float* aPtr = A  + (long)(rowBase + lr) * p.lda + lc;
    const float* bPtr = Bm + (long)(colBase + lr) * p.ldb + lc;

    u64 acc[8][4];
#pragma unroll
    for (int i = 0; i < 8; i++)
#pragma unroll
        for (int j = 0; j < 4; j++) acc[i][j] = 0ULL;

    // prologue: stage first chunk
    float4 av = *(const float4*)(aPtr + (k_begin << 3));
    float4 bv = *(const float4*)(bPtr + (k_begin << 3));
    As2[0][lc + 0][lr] = pack2(av.x); As2[0][lc + 1][lr] = pack2(av.y);
    As2[0][lc + 2][lr] = pack2(av.z); As2[0][lc + 3][lr] = pack2(av.w);
    Bs[0][lc + 0][lr] = bv.x; Bs[0][lc + 1][lr] = bv.y;
    Bs[0][lc + 2][lr] = bv.z; Bs[0][lc + 3][lr] = bv.w;
    __syncthreads();

    for (int t = k_begin; t < k_end; t++) {
        const int cur = (t - k_begin) & 1;
        if (t + 1 < k_end) {
            av = *(const float4*)(aPtr + ((t + 1) << 3));
            bv = *(const float4*)(bPtr + ((t + 1) << 3));
        }
#pragma unroll
        for (int kk = 0; kk < 8; kk++) {
            const u64* ap = &As2[cur][kk][ty << 3];
            ulonglong2 a01 = *(const ulonglong2*)(ap + 0);
            ulonglong2 a23 = *(const ulonglong2*)(ap + 2);
            ulonglong2 a45 = *(const ulonglong2*)(ap + 4);
            ulonglong2 a67 = *(const ulonglong2*)(ap + 6);
            ulonglong2 q0 = *(const ulonglong2*)&Bs[cur][kk][tx << 3];
            ulonglong2 q1 = *(const ulonglong2*)&Bs[cur][kk][(tx << 3) + 4];
            const u64 bb0 = q0.x, bb1 = q0.y, bb2 = q1.x, bb3 = q1.y;
            u64 aa[8] = {a01.x, a01.y, a23.x, a23.y, a45.x, a45.y, a67.x, a67.y};
#pragma unroll
            for (int i = 0; i < 8; i++) {
                ffma2(acc[i][0], aa[i], bb0);
                ffma2(acc[i][1], aa[i], bb1);
                ffma2(acc[i][2], aa[i], bb2);
                ffma2(acc[i][3], aa[i], bb3);
            }
        }
        if (t + 1 < k_end) {
            const int nxt = cur ^ 1;
            As2[nxt][lc + 0][lr] = pack2(av.x); As2[nxt][lc + 1][lr] = pack2(av.y);
            As2[nxt][lc + 2][lr] = pack2(av.z); As2[nxt][lc + 3][lr] = pack2(av.w);
            Bs[nxt][lc + 0][lr] = bv.x; Bs[nxt][lc + 1][lr] = bv.y;
            Bs[nxt][lc + 2][lr] = bv.z; Bs[nxt][lc + 3][lr] = bv.w;
            __syncthreads();
        }
    }

#pragma unroll
    for (int i = 0; i < 8; i++) {
        const int m = rowBase + (ty << 3) + i;
        float vals[8];
#pragma unroll
        for (int pq = 0; pq < 4; pq++) {
            float2 f = unpk(acc[i][pq]);
            vals[2 * pq] = f.x; vals[2 * pq + 1] = f.y;
        }
#pragma unroll
        for (int j8 = 0; j8 < 8; j8++) {
            const int n = colBase + (tx << 3) + j8;
            float v = vals[j8];
            if (MODE == 0) {
                v += p.bias[n];
                v = (v >= 0.f) ? v : 0.01f * v;
            } else if (MODE == 2) {
                if (n >= L) v = 0.f;
                else {
                    float xy = -v;
                    if (xy > 1.03f) {
                        v = 1.0f;   // x2 < 0.8 guaranteed -> thr=0 -> exp(0)=1
                    } else {
                        xy = fmaxf(xy, 1.0f);
                        float w  = xy + sqrtf(xy * xy - 1.0f + 1e-7f);
                        float x2v = 1.0f / w;
                        v = (x2v > 0.8f) ? expf(x2v) : 1.0f;
                    }
                }
            }
            // MODE 1 / 3 / 4: raw accumulator out
            vals[j8] = v;
        }
        if (MODE == 2) {
            float rp = ((vals[0] + vals[1]) + (vals[2] + vals[3])) +
                       ((vals[4] + vals[5]) + (vals[6] + vals[7]));
            rp += __shfl_down_sync(0xffffffffu, rp, 8, 16);
            rp += __shfl_down_sync(0xffffffffu, rp, 4, 16);
            rp += __shfl_down_sync(0xffffffffu, rp, 2, 16);
            rp += __shfl_down_sync(0xffffffffu, rp, 1, 16);
            if (tx == 0) atomicAdd(&p.denom[z * TT + m], rp);
        }
        float4* dst = (float4*)&C[(long)m * p.ldc + colBase + (tx << 3)];
        dst[0] = make_float4(vals[0], vals[1], vals[2], vals[3]);
        dst[1] = make_float4(vals[4], vals[5], vals[6], vals[7]);
    }
}

/* ---------------- small kernels ---------------- */
__global__ void zero_denom(float* denom) {
    denom[blockIdx.x * 1024 + threadIdx.x] = 0.f;
}

__global__ void prep_gwT(const float* gw1, const float* gw2, float* gwT) {
    int idx = blockIdx.x * 256 + threadIdx.x;
    if (idx >= 256 * DHP) return;
    int r = idx / DHP, k = idx % DHP;
    float v = 0.f;
    if (k < 257) v = (r < 128) ? gw1[k * 128 + r] : gw2[k * 128 + (r - 128)];
    gwT[idx] = v;
}

__global__ void proj_kernel(const float* xv2p, const float* inputs,
                            const float* b2, float* proj, float* qproj) {
    const int row = blockIdx.x;
    const int tid = threadIdx.x;  // 256
    float x;
    if (tid < 128) {
        float v = xv2p[row * D2C + tid]
                + xv2p[(size_t)M_ROWS * D2C + row * D2C + tid]
                + b2[tid];
        x = (v >= 0.f) ? v : 0.01f * v;
    } else {
        x = inputs[(long)row * IN_C + DVC + (tid - 128)];
    }
    // block reduction of x*x via shuffles
    float ss = x * x;
    for (int o = 16; o > 0; o >>= 1) ss += __shfl_down_sync(0xffffffffu, ss, o);
    __shared__ float red[8];
    if ((tid & 31) == 0) red[tid >> 5] = ss;
    __syncthreads();
    __shared__ float nrm;
    if (tid == 0) {
        float t = ((red[0] + red[1]) + (red[2] + red[3])) +
                  ((red[4] + red[5]) + (red[6] + red[7]));
        nrm = sqrtf(fmaxf(t, 1e-12f));
    }
    __syncthreads();
    float nn = nrm;
    float sh = sinhf(nn) / nn;
    float* pr = proj  + (long)row * DHP;
    float* qr = qproj + (long)row * DHP;
    float val = sh * x;
    pr[1 + tid] = val;
    qr[1 + tid] = val;
    if (tid == 0) { float ch = coshf(nn); pr[0] = ch; qr[0] = -ch; }
    if (tid < 7)  { pr[257 + tid] = 0.f; qr[257 + tid] = 0.f; }
}

__global__ void transpose_g1(const float* g12, float* g1T) {
    __shared__ float tile[32][33];
    int b = blockIdx.z;
    int t0 = blockIdx.x * 32, n0 = blockIdx.y * 32;
    for (int r = threadIdx.y; r < 32; r += 8)
        tile[r][threadIdx.x] = g12[((long)(b * TT + t0 + r)) * 256 + n0 + threadIdx.x];
    __syncthreads();
    for (int r = threadIdx.y; r < 32; r += 8)
        g1T[(long)b * DGC * TT + (long)(n0 + r) * TT + t0 + threadIdx.x] = tile[threadIdx.x][r];
}

// disadj @ y via windowed forward+backward exponential scan (r^128 ~ 4e-21)
#define SC 64
#define SHALO 128
__global__ void scan_kernel(const float* g12, float* x2) {
    const int b = blockIdx.x;
    const int c = blockIdx.y;
    const int ch = threadIdx.x;        // 128 channels
    const float r = 0.69220062755534635f;  // exp(-exp(-1))
    __shared__ float sf[SC][DGC];
    const int s = c * SC;
    int i0 = s - SHALO; if (i0 < 0) i0 = 0;
    float f = 0.f;
    for (int i = i0; i < s + SC; i++) {
        float y = g12[((long)(b * TT + i)) * 256 + 128 + ch];
        f = fmaf(r, f, y);
        if (i >= s) sf[i - s][ch] = f;
    }
    int i1 = s + SC + SHALO; if (i1 > TT) i1 = TT;
    float bk = 0.f;
    for (int i = i1 - 1; i >= s; i--) {
        float y = g12[((long)(b * TT + i)) * 256 + 128 + ch];
        bk = fmaf(r, bk, y);
        if (i < s + SC) {
            float v = sf[i - s][ch] + bk - y;
            v = (v >= 0.f) ? v : 0.01f * v;
            x2[((long)(b * TT + i)) * DGC + ch] = v;
        }
    }
}

__global__ void frame_kernel(const float* x1p, const float* x2,
                             const float* denom, const int* seq,
                             const float* cls_w, const float* cls_b,
                             float* frame, float* out) {
    int warp = threadIdx.x >> 5, lane = threadIdx.x & 31;
    int row = blockIdx.x * 8 + warp;
    const int b = row >> 11;           // row / TT
    const int m = row & (TT - 1);
    const int L = seq[b];
    float s = 0.f;
    if (m < L) {
        float inv = 1.0f / denom[row];
        const float* p0 = x1p + (size_t)row * DGC;
        const float* p1 = p0 + (size_t)M_ROWS * DGC;
        for (int d = lane; d < DGC; d += 32) {
            float v = (p0[d] + p1[d]) * inv;
            v = (v >= 0.f) ? v : 0.01f * v;
            float sg = (d == 0) ? -1.0f : 1.0f;
            s += sg * v * cls_w[d];
        }
    }
    const float* xr2 = x2 + (size_t)row * DGC;
    for (int d = lane; d < DGC; d += 32)
        s += xr2[d] * cls_w[DGC + d];
    for (int o = 16; o > 0; o >>= 1) s += __shfl_down_sync(0xffffffffu, s, o);
    if (lane == 0) {
        float v = 2.0f + 2.0f * s + cls_b[0];
        frame[row] = v;
        out[8 + row] = v;
    }
}

__global__ void clas_kernel(const float* frame, const int* seq_len, float* out) {
    __shared__ float s[TT];
    __shared__ float red[1024];
    const int b = blockIdx.x, tid = threadIdx.x;
    const int L = seq_len[b];
    for (int t = tid; t < TT; t += 1024)
        s[t] = (t < L) ? frame[b * TT + t] : -1e30f;
    __syncthreads();
    for (int size = 2; size <= TT; size <<= 1) {
        for (int stride = size >> 1; stride > 0; stride >>= 1) {
            for (int i = tid; i < TT; i += 1024) {
                int l = i ^ stride;
                if (l > i) {
                    float a = s[i], c = s[l];
                    bool desc = ((i & size) == 0);
                    if (desc ? (a < c) : (a > c)) { s[i] = c; s[l] = a; }
                }
            }
            __syncthreads();
        }
    }
    int k = L / 16 + 1;
    float ps = 0.f;
    for (int t = tid; t < k; t += 1024) ps += s[t];
    red[tid] = ps;
    __syncthreads();
    for (int st = 512; st > 0; st >>= 1) {
        if (tid < st) red[tid] += red[tid + st];
        __syncthreads();
    }
    if (tid == 0) {
        float m = red[0] / (float)k;
        out[b] = 1.0f / (1.0f + expf(-m));
    }
}

/* ---------------- host orchestration ---------------- */
extern "C" void kernel_launch(void* const* d_in, const int* in_sizes, int n_in,
                              void* d_out, int out_size) {
    const float* inputs = (const float*)d_in[0];
    const int*   seq    = (const int*)d_in[1];
    const float* w1     = (const float*)d_in[2];
    const float* b1     = (const float*)d_in[3];
    const float* w2     = (const float*)d_in[4];
    const float* b2     = (const float*)d_in[5];
    const float* gw1    = (const float*)d_in[6];
    const float* gw2    = (const float*)d_in[7];
    const float* cls_w  = (const float*)d_in[8];
    const float* cls_b  = (const float*)d_in[9];
    float* out = (float*)d_out;

    float *y1, *xv2p, *proj, *qproj, *gwT, *g12, *g1T, *E, *denom, *x1p, *x2, *frame;
    cudaGetSymbolAddress((void**)&y1,    g_y1);
    cudaGetSymbolAddress((void**)&xv2p,  g_xv2p);
    cudaGetSymbolAddress((void**)&proj,  g_proj);
    cudaGetSymbolAddress((void**)&qproj, g_qproj);
    cudaGetSymbolAddress((void**)&gwT,   g_gwT);
    cudaGetSymbolAddress((void**)&g12,   g_g12);
    cudaGetSymbolAddress((void**)&g1T,   g_g1T);
    cudaGetSymbolAddress((void**)&E,     g_E);
    cudaGetSymbolAddress((void**)&denom, g_denom);
    cudaGetSymbolAddress((void**)&x1p,   g_x1p);
    cudaGetSymbolAddress((void**)&x2,    g_x2);
    cudaGetSymbolAddress((void**)&frame, g_frame);

    zero_denom<<<M_ROWS / 1024, 1024>>>(denom);
    prep_gwT<<<(256 * DHP + 255) / 256, 256>>>(gw1, gw2, gwT);

    // GEMM1: y1 = leaky(inputs[:, :1024] @ w1^T + b1)   M=16384 N=512 K=1024
    {
        GemmP p = { inputs, w1, y1, DVC, IN_C, DVC, D1C, 0, 0, 0, 0, b1, nullptr, nullptr };
        sgemm<0><<<dim3(D1C / 128, M_ROWS / 128, 1), 256>>>(p);
    }
    // GEMM2 raw partials, split-K(2):  M=16384 N=128 K=512 -> 2x256
    {
        GemmP p = { y1, w2, xv2p, D1C, D1C, D1C, D2C, 0, 0, 0,
                    (long)M_ROWS * D2C, nullptr, nullptr, nullptr };
        sgemm<4><<<dim3(2, M_ROWS / 128, 1), 256>>>(p);
    }
    // combine partials + bias + leaky + Lorentz expmap
    proj_kernel<<<M_ROWS, 256>>>(xv2p, inputs, b2, proj, qproj);

    // g12 = proj @ [gw1 | gw2]   M=16384 N=256 K=264
    {
        GemmP p = { proj, gwT, g12, DHP, DHP, DHP, 256, 0, 0, 0, 0, nullptr, nullptr, nullptr };
        sgemm<1><<<dim3(2, M_ROWS / 128, 1), 256>>>(p);
    }
    transpose_g1<<<dim3(TT / 32, DGC / 32, BB), dim3(32, 8)>>>(g12, g1T);

    // similarity -> E (tile-skipped) + fused denom atomics
    {
        GemmP p = { qproj, proj, E, DHP, DHP, DHP, TT,
                    (long)TT * DHP, (long)TT * DHP, (long)TT * TT, 0,
                    nullptr, seq, denom };
        sgemm<2><<<dim3(TT / 128, TT / 128, BB), 256>>>(p);
    }
    // x1 raw partials = E @ g1T, split-K(2), K clamped to ceil8(L)
    {
        GemmP p = { E, g1T, x1p, TT, TT, TT, DGC,
                    (long)TT * TT, (long)DGC * TT, (long)TT * DGC,
                    (long)M_ROWS * DGC, nullptr, seq, nullptr };
        sgemm<3><<<dim3(2, TT / 128, BB), 256>>>(p);
    }
    // x2 = leaky(disadj @ g2) via windowed exponential scan
    scan_kernel<<<dim3(BB, TT / SC), DGC>>>(g12, x2);

    // frame_prob: combine split-K partials, /denom, leaky, classifier dot
    frame_kernel<<<M_ROWS / 8, 256>>>(x1p, x2, denom, seq, cls_w, cls_b, frame, out);
    clas_kernel<<<BB, 1024>>>(frame, seq, out);
}

// round 11
// speedup vs baseline: 1.2068x; 1.2068x over previous
#include <cuda_runtime.h>
#include <math.h>

#define BB 8
#define TT 2048
#define M_ROWS (BB*TT)   /* 16384 */
#define DVC 1024
#define DAC 128
#define IN_C 1152
#define D1C 512
#define D2C 128
#define DHP 272          /* 257 padded to mult of 16 */
#define DGC 128

typedef unsigned long long u64;

/* ---------------- scratch (static device globals; no allocs) ---------------- */
__device__ float g_y1[M_ROWS * D1C];
__device__ float g_xv2[M_ROWS * D2C];
__device__ float g_proj[M_ROWS * DHP];
__device__ float g_qproj[M_ROWS * DHP];
__device__ float g_gwT[256 * DHP];
__device__ float g_g12[M_ROWS * 256];
__device__ float g_g1T[BB * DGC * TT];
__device__ float g_E[(size_t)BB * TT * TT]; // 134 MB
__device__ float g_denom[M_ROWS];
__device__ float g_x1p[2 * M_ROWS * DGC];   // adj split-K raw partials
__device__ float g_x2[M_ROWS * DGC];
__device__ float g_frame[M_ROWS];

/* ---------------- packed f32x2 helpers (Blackwell FFMA2) ---------------- */
__device__ __forceinline__ void ffma2(u64 &d, u64 a, u64 b) {
    asm("fma.rn.f32x2 %0, %1, %2, %0;" : "+l"(d) : "l"(a), "l"(b));
}
__device__ __forceinline__ u64 pack2(float x) {
    u64 r; asm("mov.b64 %0, {%1, %1};" : "=l"(r) : "f"(x)); return r;
}
__device__ __forceinline__ float2 unpk(u64 v) {
    float2 r; asm("mov.b64 {%0, %1}, %2;" : "=f"(r.x), "=f"(r.y) : "l"(v)); return r;
}

/* -------- generic 128x128 SGEMM, K-chunk 16, C = A[M,K] * B[N,K]^T -------- */
struct GemmP {
    const float* A; const float* Bm; float* C;
    int K, lda, ldb, ldc;
    long aS, bS, cS;            // per-blockIdx.z strides
    long splitStride;           // MODE3: offset between K-split partial buffers
    const float* bias;
    const int* seq;
    float* denom;               // MODE2: atomic row-sum output
};

// MODE 0: C = leaky(acc + bias[n])
// MODE 1: C = acc
// MODE 2: similarity -> E (tile-skipped by seq_len) + fused row-sum atomics
// MODE 3: raw adj matmul partials, split-K over gridDim.x, K clamped to ceil16(L)
template <int MODE>
__global__ __launch_bounds__(256, 2) void sgemm(GemmP p) {
    const int z = blockIdx.z;
    const int rowBase = blockIdx.y << 7;
    int colBase, split;
    if (MODE == 3) { colBase = 0; split = blockIdx.x; }
    else           { colBase = blockIdx.x << 7; split = 0; }

    int L = 0;
    if (MODE >= 2) L = p.seq[z];
    if (MODE == 2 && (rowBase >= L || colBase >= L)) return;   // tile never read
    if (MODE == 3 && rowBase >= L) return;                     // output rows masked

    int k_begin = 0, k_end = p.K >> 4;      // chunks of 16
    if (MODE == 3) {
        const int nk_eff = (L + 15) >> 4;   // E cols >= ceil16(L) are zero
        const int half   = (nk_eff + 1) >> 1;
        k_begin = split ? half : 0;
        k_end   = split ? nk_eff : half;
    }

    __shared__ float As[2][16][128];
    __shared__ float Bs[2][16][128];
    const float* A  = p.A  + (long)z * p.aS;
    const float* Bm = p.Bm + (long)z * p.bS;
    float*       C  = p.C  + (long)z * p.cS + (long)split * p.splitStride;
    const int tid = threadIdx.x;
    const int tx = tid & 15, ty = tid >> 4;
    const int lr = tid >> 1;
    const int lc = (tid & 1) << 3;          // 0 or 8
    const float* aPtr = A  + (long)(rowBase + lr) * p.lda + lc;
    const float* bPtr = Bm + (long)(colBase + lr) * p.ldb + lc;

    u64 acc[8][4];
#pragma unroll
    for (int i = 0; i < 8; i++)
#pragma unroll
        for (int j = 0; j < 4; j++) acc[i][j] = 0ULL;

    // prologue: stage first chunk
    float4 av0 = *(const float4*)(aPtr + (k_begin << 4));
    float4 av1 = *(const float4*)(aPtr + (k_begin << 4) + 4);
    float4 bv0 = *(const float4*)(bPtr + (k_begin << 4));
    float4 bv1 = *(const float4*)(bPtr + (k_begin << 4) + 4);
    As[0][lc + 0][lr] = av0.x; As[0][lc + 1][lr] = av0.y;
    As[0][lc + 2][lr] = av0.z; As[0][lc + 3][lr] = av0.w;
    As[0][lc + 4][lr] = av1.x; As[0][lc + 5][lr] = av1.y;
    As[0][lc + 6][lr] = av1.z; As[0][lc + 7][lr] = av1.w;
    Bs[0][lc + 0][lr] = bv0.x; Bs[0][lc + 1][lr] = bv0.y;
    Bs[0][lc + 2][lr] = bv0.z; Bs[0][lc + 3][lr] = bv0.w;
    Bs[0][lc + 4][lr] = bv1.x; Bs[0][lc + 5][lr] = bv1.y;
    Bs[0][lc + 6][lr] = bv1.z; Bs[0][lc + 7][lr] = bv1.w;
    __syncthreads();

    for (int t = k_begin; t < k_end; t++) {
        const int cur = (t - k_begin) & 1;
        if (t + 1 < k_end) {
            av0 = *(const float4*)(aPtr + ((t + 1) << 4));
            av1 = *(const float4*)(aPtr + ((t + 1) << 4) + 4);
            bv0 = *(const float4*)(bPtr + ((t + 1) << 4));
            bv1 = *(const float4*)(bPtr + ((t + 1) << 4) + 4);
        }
#pragma unroll
        for (int kk = 0; kk < 16; kk++) {
            float4 a0 = *(const float4*)&As[cur][kk][ty << 3];
            float4 a1 = *(const float4*)&As[cur][kk][(ty << 3) + 4];
            ulonglong2 q0 = *(const ulonglong2*)&Bs[cur][kk][tx << 3];
            ulonglong2 q1 = *(const ulonglong2*)&Bs[cur][kk][(tx << 3) + 4];
            const u64 bb0 = q0.x, bb1 = q0.y, bb2 = q1.x, bb3 = q1.y;
            float aa[8] = {a0.x, a0.y, a0.z, a0.w, a1.x, a1.y, a1.z, a1.w};
#pragma unroll
            for (int i = 0; i < 8; i++) {
                u64 a2 = pack2(aa[i]);
                ffma2(acc[i][0], a2, bb0);
                ffma2(acc[i][1], a2, bb1);
                ffma2(acc[i][2], a2, bb2);
                ffma2(acc[i][3], a2, bb3);
            }
        }
        if (t + 1 < k_end) {
            const int nxt = cur ^ 1;
            As[nxt][lc + 0][lr] = av0.x; As[nxt][lc + 1][lr] = av0.y;
            As[nxt][lc + 2][lr] = av0.z; As[nxt][lc + 3][lr] = av0.w;
            As[nxt][lc + 4][lr] = av1.x; As[nxt][lc + 5][lr] = av1.y;
            As[nxt][lc + 6][lr] = av1.z; As[nxt][lc + 7][lr] = av1.w;
            Bs[nxt][lc + 0][lr] = bv0.x; Bs[nxt][lc + 1][lr] = bv0.y;
            Bs[nxt][lc + 2][lr] = bv0.z; Bs[nxt][lc + 3][lr] = bv0.w;
            Bs[nxt][lc + 4][lr] = bv1.x; Bs[nxt][lc + 5][lr] = bv1.y;
            Bs[nxt][lc + 6][lr] = bv1.z; Bs[nxt][lc + 7][lr] = bv1.w;
            __syncthreads();
        }
    }

#pragma unroll
    for (int i = 0; i < 8; i++) {
        const int m = rowBase + (ty << 3) + i;
        float vals[8];
#pragma unroll
        for (int pq = 0; pq < 4; pq++) {
            float2 f = unpk(acc[i][pq]);
            vals[2 * pq] = f.x; vals[2 * pq + 1] = f.y;
        }
#pragma unroll
        for (int j8 = 0; j8 < 8; j8++) {
            const int n = colBase + (tx << 3) + j8;
            float v = vals[j8];
            if (MODE == 0) {
                v += p.bias[n];
                v = (v >= 0.f) ? v : 0.01f * v;
            } else if (MODE == 2) {
                if (n >= L) v = 0.f;
                else {
                    float xy = -v;
                    if (xy > 1.03f) {
                        v = 1.0f;   // x2 < 0.8 guaranteed -> thr=0 -> exp(0)=1
                    } else {
                        xy = fmaxf(xy, 1.0f);
                        float w  = xy + sqrtf(xy * xy - 1.0f + 1e-7f);
                        float x2v = 1.0f / w;
                        v = (x2v > 0.8f) ? expf(x2v) : 1.0f;
                    }
                }
            }
            // MODE 1 / 3: raw accumulator out
            vals[j8] = v;
        }
        if (MODE == 2) {
            float rp = ((vals[0] + vals[1]) + (vals[2] + vals[3])) +
                       ((vals[4] + vals[5]) + (vals[6] + vals[7]));
            rp += __shfl_down_sync(0xffffffffu, rp, 8, 16);
            rp += __shfl_down_sync(0xffffffffu, rp, 4, 16);
            rp += __shfl_down_sync(0xffffffffu, rp, 2, 16);
            rp += __shfl_down_sync(0xffffffffu, rp, 1, 16);
            if (tx == 0) atomicAdd(&p.denom[z * TT + m], rp);
        }
        float4* dst = (float4*)&C[(long)m * p.ldc + colBase + (tx << 3)];
        dst[0] = make_float4(vals[0], vals[1], vals[2], vals[3]);
        dst[1] = make_float4(vals[4], vals[5], vals[6], vals[7]);
    }
}

/* ---------------- small kernels ---------------- */
__global__ void zero_denom(float* denom) {
    denom[blockIdx.x * 1024 + threadIdx.x] = 0.f;
}

__global__ void prep_gwT(const float* gw1, const float* gw2, float* gwT) {
    int idx = blockIdx.x * 256 + threadIdx.x;
    if (idx >= 256 * DHP) return;
    int r = idx / DHP, k = idx % DHP;
    float v = 0.f;
    if (k < 257) v = (r < 128) ? gw1[k * 128 + r] : gw2[k * 128 + (r - 128)];
    gwT[idx] = v;
}

__global__ void proj_kernel(const float* xv2, const float* inputs,
                            float* proj, float* qproj) {
    const int row = blockIdx.x;
    const int tid = threadIdx.x;  // 256
    float x = (tid < 128) ? xv2[row * 128 + tid]
                          : inputs[(long)row * IN_C + DVC + (tid - 128)];
    float ss = x * x;
    for (int o = 16; o > 0; o >>= 1) ss += __shfl_down_sync(0xffffffffu, ss, o);
    __shared__ float red[8];
    if ((tid & 31) == 0) red[tid >> 5] = ss;
    __syncthreads();
    __shared__ float nrm;
    if (tid == 0) {
        float t = ((red[0] + red[1]) + (red[2] + red[3])) +
                  ((red[4] + red[5]) + (red[6] + red[7]));
        nrm = sqrtf(fmaxf(t, 1e-12f));
    }
    __syncthreads();
    float nn = nrm;
    float sh = sinhf(nn) / nn;
    float* pr = proj  + (long)row * DHP;
    float* qr = qproj + (long)row * DHP;
    float val = sh * x;
    pr[1 + tid] = val;
    qr[1 + tid] = val;
    if (tid == 0) { float ch = coshf(nn); pr[0] = ch; qr[0] = -ch; }
    if (tid < 15) { pr[257 + tid] = 0.f; qr[257 + tid] = 0.f; }
}

__global__ void transpose_g1(const float* g12, float* g1T) {
    __shared__ float tile[32][33];
    int b = blockIdx.z;
    int t0 = blockIdx.x * 32, n0 = blockIdx.y * 32;
    for (int r = threadIdx.y; r < 32; r += 8)
        tile[r][threadIdx.x] = g12[((long)(b * TT + t0 + r)) * 256 + n0 + threadIdx.x];
    __syncthreads();
    for (int r = threadIdx.y; r < 32; r += 8)
        g1T[(long)b * DGC * TT + (long)(n0 + r) * TT + t0 + threadIdx.x] = tile[threadIdx.x][r];
}

// disadj @ y via windowed forward+backward exponential scan (r^128 ~ 4e-21)
#define SC 64
#define SHALO 128
__global__ void scan_kernel(const float* g12, float* x2) {
    const int b = blockIdx.x;
    const int c = blockIdx.y;
    const int ch = threadIdx.x;        // 128 channels
    const float r = 0.69220062755534635f;  // exp(-exp(-1))
    __shared__ float sf[SC][DGC];
    const int s = c * SC;
    int i0 = s - SHALO; if (i0 < 0) i0 = 0;
    float f = 0.f;
    for (int i = i0; i < s + SC; i++) {
        float y = g12[((long)(b * TT + i)) * 256 + 128 + ch];
        f = fmaf(r, f, y);
        if (i >= s) sf[i - s][ch] = f;
    }
    int i1 = s + SC + SHALO; if (i1 > TT) i1 = TT;
    float bk = 0.f;
    for (int i = i1 - 1; i >= s; i--) {
        float y = g12[((long)(b * TT + i)) * 256 + 128 + ch];
        bk = fmaf(r, bk, y);
        if (i < s + SC) {
            float v = sf[i - s][ch] + bk - y;
            v = (v >= 0.f) ? v : 0.01f * v;
            x2[((long)(b * TT + i)) * DGC + ch] = v;
        }
    }
}

__global__ void frame_kernel(const float* x1p, const float* x2,
                             const float* denom, const int* seq,
                             const float* cls_w, const float* cls_b,
                             float* frame, float* out) {
    int warp = threadIdx.x >> 5, lane = threadIdx.x & 31;
    int row = blockIdx.x * 8 + warp;
    const int b = row >> 11;           // row / TT
    const int m = row & (TT - 1);
    const int L = seq[b];
    float s = 0.f;
    if (m < L) {
        float inv = 1.0f / denom[row];
        const float* p0 = x1p + (size_t)row * DGC;
        const float* p1 = p0 + (size_t)M_ROWS * DGC;
        for (int d = lane; d < DGC; d += 32) {
            float v = (p0[d] + p1[d]) * inv;
            v = (v >= 0.f) ? v : 0.01f * v;
            float sg = (d == 0) ? -1.0f : 1.0f;
            s += sg * v * cls_w[d];
        }
    }
    const float* xr2 = x2 + (size_t)row * DGC;
    for (int d = lane; d < DGC; d += 32)
        s += xr2[d] * cls_w[DGC + d];
    for (int o = 16; o > 0; o >>= 1) s += __shfl_down_sync(0xffffffffu, s, o);
    if (lane == 0) {
        float v = 2.0f + 2.0f * s + cls_b[0];
        frame[row] = v;
        out[8 + row] = v;
    }
}

__global__ void clas_kernel(const float* frame, const int* seq_len, float* out) {
    __shared__ float s[TT];
    __shared__ float red[1024];
    const int b = blockIdx.x, tid = threadIdx.x;
    const int L = seq_len[b];
    for (int t = tid; t < TT; t += 1024)
        s[t] = (t < L) ? frame[b * TT + t] : -1e30f;
    __syncthreads();
    for (int size = 2; size <= TT; size <<= 1) {
        for (int stride = size >> 1; stride > 0; stride >>= 1) {
            for (int i = tid; i < TT; i += 1024) {
                int l = i ^ stride;
                if (l > i) {
                    float a = s[i], c = s[l];
                    bool desc = ((i & size) == 0);
                    if (desc ? (a < c) : (a > c)) { s[i] = c; s[l] = a; }
                }
            }
            __syncthreads();
        }
    }
    int k = L / 16 + 1;
    float ps = 0.f;
    for (int t = tid; t < k; t += 1024) ps += s[t];
    red[tid] = ps;
    __syncthreads();
    for (int st = 512; st > 0; st >>= 1) {
        if (tid < st) red[tid] += red[tid + st];
        __syncthreads();
    }
    if (tid == 0) {
        float m = red[0] / (float)k;
        out[b] = 1.0f / (1.0f + expf(-m));
    }
}

/* ---------------- host orchestration ---------------- */
extern "C" void kernel_launch(void* const* d_in, const int* in_sizes, int n_in,
                              void* d_out, int out_size) {
    const float* inputs = (const float*)d_in[0];
    const int*   seq    = (const int*)d_in[1];
    const float* w1     = (const float*)d_in[2];
    const float* b1     = (const float*)d_in[3];
    const float* w2     = (const float*)d_in[4];
    const float* b2     = (const float*)d_in[5];
    const float* gw1    = (const float*)d_in[6];
    const float* gw2    = (const float*)d_in[7];
    const float* cls_w  = (const float*)d_in[8];
    const float* cls_b  = (const float*)d_in[9];
    float* out = (float*)d_out;

    float *y1, *xv2, *proj, *qproj, *gwT, *g12, *g1T, *E, *denom, *x1p, *x2, *frame;
    cudaGetSymbolAddress((void**)&y1,    g_y1);
    cudaGetSymbolAddress((void**)&xv2,   g_xv2);
    cudaGetSymbolAddress((void**)&proj,  g_proj);
    cudaGetSymbolAddress((void**)&qproj, g_qproj);
    cudaGetSymbolAddress((void**)&gwT,   g_gwT);
    cudaGetSymbolAddress((void**)&g12,   g_g12);
    cudaGetSymbolAddress((void**)&g1T,   g_g1T);
    cudaGetSymbolAddress((void**)&E,     g_E);
    cudaGetSymbolAddress((void**)&denom, g_denom);
    cudaGetSymbolAddress((void**)&x1p,   g_x1p);
    cudaGetSymbolAddress((void**)&x2,    g_x2);
    cudaGetSymbolAddress((void**)&frame, g_frame);

    zero_denom<<<M_ROWS / 1024, 1024>>>(denom);
    prep_gwT<<<(256 * DHP + 255) / 256, 256>>>(gw1, gw2, gwT);

    // GEMM1: y1 = leaky(inputs[:, :1024] @ w1^T + b1)   M=16384 N=512 K=1024
    {
        GemmP p = { inputs, w1, y1, DVC, IN_C, DVC, D1C, 0, 0, 0, 0, b1, nullptr, nullptr };
        sgemm<0><<<dim3(D1C / 128, M_ROWS / 128, 1), 256>>>(p);
    }
    // GEMM2: xv2 = leaky(y1 @ w2^T + b2)   M=16384 N=128 K=512
    {
        GemmP p = { y1, w2, xv2, D1C, D1C, D1C, D2C, 0, 0, 0, 0, b2, nullptr, nullptr };
        sgemm<0><<<dim3(1, M_ROWS / 128, 1), 256>>>(p);
    }
    proj_kernel<<<M_ROWS, 256>>>(xv2, inputs, proj, qproj);

    // g12 = proj @ [gw1 | gw2]   M=16384 N=256 K=272
    {
        GemmP p = { proj, gwT, g12, DHP, DHP, DHP, 256, 0, 0, 0, 0, nullptr, nullptr, nullptr };
        sgemm<1><<<dim3(2, M_ROWS / 128, 1), 256>>>(p);
    }
    transpose_g1<<<dim3(TT / 32, DGC / 32, BB), dim3(32, 8)>>>(g12, g1T);

    // similarity -> E (tile-skipped) + fused denom atomics   K=272
    {
        GemmP p = { qproj, proj, E, DHP, DHP, DHP, TT,
                    (long)TT * DHP, (long)TT * DHP, (long)TT * TT, 0,
                    nullptr, seq, denom };
        sgemm<2><<<dim3(TT / 128, TT / 128, BB), 256>>>(p);
    }
    // x1 raw partials = E @ g1T, split-K(2), K clamped to ceil16(L)
    {
        GemmP p = { E, g1T, x1p, TT, TT, TT, DGC,
                    (long)TT * TT, (long)DGC * TT, (long)TT * DGC,
                    (long)M_ROWS * DGC, nullptr, seq, nullptr };
        sgemm<3><<<dim3(2, TT / 128, BB), 256>>>(p);
    }
    // x2 = leaky(disadj @ g2) via windowed exponential scan
    scan_kernel<<<dim3(BB, TT / SC), DGC>>>(g12, x2);

    // frame_prob: combine split-K partials, /denom, leaky, classifier dot
    frame_kernel<<<M_ROWS / 8, 256>>>(x1p, x2, denom, seq, cls_w, cls_b, frame, out);
    clas_kernel<<<BB, 1024>>>(frame, seq, out);
}